// round 1
// baseline (speedup 1.0000x reference)
#include <cuda_runtime.h>
#include <cstdint>

#define Bb 32
#define Nn 1024
#define Tt 32
#define Ff 5
#define Hh 64
#define Rr 5
#define BN (Bb*Nn)

// Scratch (static __device__: no allocation allowed)
__device__ float g_eold[(size_t)BN * Hh];   // [B*N, H]  8 MB
__device__ float g_coef[(size_t)Nn * Nn];   // [N, N]    4 MB
__device__ float g_deg[Nn];

__device__ __forceinline__ float sigmoidf_(float v) {
    return 1.0f / (1.0f + __expf(-v));
}

// ---------------------------------------------------------------------------
// Kernel 1: edge gates.  coef[i,j] = mask(i,j) * leaky_relu(A[i,j,:]·w + b),
// deg[i] = sum_j mask(i,j)
// ---------------------------------------------------------------------------
__global__ __launch_bounds__(256) void prep_kernel(
    const float* __restrict__ A,
    const float* __restrict__ gnn_w,
    const float* __restrict__ gnn_b)
{
    const int i = blockIdx.x;
    const float gw0 = gnn_w[0], gw1 = gnn_w[1], gw2 = gnn_w[2],
                gw3 = gnn_w[3], gw4 = gnn_w[4];
    const float gb = gnn_b[0];
    float degloc = 0.f;
    for (int j = threadIdx.x; j < Nn; j += 256) {
        const float* a = A + ((size_t)i * Nn + j) * Rr;
        float a0 = a[0], a1 = a[1], a2 = a[2], a3 = a[3], a4 = a[4];
        float s = a0 + a1 + a2 + a3 + a4;
        float z = gb + a0 * gw0 + a1 * gw1 + a2 * gw2 + a3 * gw3 + a4 * gw4;
        float w = z > 0.f ? z : 0.2f * z;
        float m = s > 0.f ? 1.f : 0.f;
        g_coef[(size_t)i * Nn + j] = m * w;
        degloc += m;
    }
    __shared__ float red[256];
    red[threadIdx.x] = degloc;
    __syncthreads();
    for (int o = 128; o > 0; o >>= 1) {
        if (threadIdx.x < o) red[threadIdx.x] += red[threadIdx.x + o];
        __syncthreads();
    }
    if (threadIdx.x == 0) g_deg[i] = red[0];
}

// ---------------------------------------------------------------------------
// Kernel 2: LSTM + temporal attention.  4 sequences per 256-thread CTA.
// Thread g owns gate row g (Whh row in registers).  h-state in smem.
// ---------------------------------------------------------------------------
__global__ __launch_bounds__(256) void lstm_kernel(
    const float* __restrict__ x,
    const float* __restrict__ Wih,
    const float* __restrict__ Whh,
    const float* __restrict__ bih,
    const float* __restrict__ bhh,
    const float* __restrict__ attn_w,
    const float* __restrict__ attn_b)
{
    __shared__ float  xs[4 * Tt * Ff];       // 2.5 KB   x for 4 sequences
    __shared__ float4 hsm4[4 * 16];          // 1 KB     h[4][64] as float4
    __shared__ float  gbuf[4][256];          // 4 KB     raw gate preacts
    __shared__ float  hist[4][Tt][Hh];       // 32 KB    h history
    __shared__ float  sbuf[4][Tt];           // 0.5 KB   scores -> attn weights

    const int tid = threadIdx.x;
    const int g   = tid;                      // gate index 0..255
    const size_t seq0 = (size_t)blockIdx.x * 4;

    // stage x for the 4 sequences (contiguous in global)
    {
        const float* xg = x + seq0 * (Tt * Ff);
        for (int idx = tid; idx < 4 * Tt * Ff; idx += 256) xs[idx] = xg[idx];
    }

    // per-thread weights
    float wih[Ff];
#pragma unroll
    for (int f = 0; f < Ff; f++) wih[f] = Wih[g * Ff + f];
    const float bias = bih[g] + bhh[g];

    float whh[Hh];
    {
        const float4* w4 = (const float4*)(Whh + (size_t)g * Hh);
#pragma unroll
        for (int q = 0; q < 16; q++) {
            float4 v = w4[q];
            whh[4*q+0] = v.x; whh[4*q+1] = v.y; whh[4*q+2] = v.z; whh[4*q+3] = v.w;
        }
    }

    ((float*)hsm4)[tid] = 0.f;          // h = 0  (256 = 4*64 floats)
    float c = 0.f;                       // this thread's cell state (s=us, j=uj)
    const int us = g >> 6, uj = g & 63;
    __syncthreads();

    for (int t = 0; t < Tt; t++) {
        float acc0 = bias, acc1 = bias, acc2 = bias, acc3 = bias;
        // input projection
#pragma unroll
        for (int f = 0; f < Ff; f++) {
            float w = wih[f];
            acc0 = fmaf(xs[0*Tt*Ff + t*Ff + f], w, acc0);
            acc1 = fmaf(xs[1*Tt*Ff + t*Ff + f], w, acc1);
            acc2 = fmaf(xs[2*Tt*Ff + t*Ff + f], w, acc2);
            acc3 = fmaf(xs[3*Tt*Ff + t*Ff + f], w, acc3);
        }
        // recurrent projection: gates[s][g] += h[s][:] . Whh[g][:]
#pragma unroll
        for (int q = 0; q < 16; q++) {
            float4 h0 = hsm4[q], h1 = hsm4[16 + q], h2 = hsm4[32 + q], h3 = hsm4[48 + q];
            float w0 = whh[4*q+0], w1 = whh[4*q+1], w2 = whh[4*q+2], w3 = whh[4*q+3];
            acc0 = fmaf(h0.x, w0, acc0); acc0 = fmaf(h0.y, w1, acc0);
            acc0 = fmaf(h0.z, w2, acc0); acc0 = fmaf(h0.w, w3, acc0);
            acc1 = fmaf(h1.x, w0, acc1); acc1 = fmaf(h1.y, w1, acc1);
            acc1 = fmaf(h1.z, w2, acc1); acc1 = fmaf(h1.w, w3, acc1);
            acc2 = fmaf(h2.x, w0, acc2); acc2 = fmaf(h2.y, w1, acc2);
            acc2 = fmaf(h2.z, w2, acc2); acc2 = fmaf(h2.w, w3, acc2);
            acc3 = fmaf(h3.x, w0, acc3); acc3 = fmaf(h3.y, w1, acc3);
            acc3 = fmaf(h3.z, w2, acc3); acc3 = fmaf(h3.w, w3, acc3);
        }
        gbuf[0][g] = acc0; gbuf[1][g] = acc1; gbuf[2][g] = acc2; gbuf[3][g] = acc3;
        __syncthreads();
        // cell/hidden update: thread owns (us, uj)
        {
            float gi = gbuf[us][uj];
            float gf = gbuf[us][64 + uj];
            float gg = gbuf[us][128 + uj];
            float go = gbuf[us][192 + uj];
            c = sigmoidf_(gf) * c + sigmoidf_(gi) * tanhf(gg);
            float h = sigmoidf_(go) * tanhf(c);
            ((float*)hsm4)[us * 64 + uj] = h;
            hist[us][t][uj] = h;
        }
        __syncthreads();
    }

    // ---- attention over time ----
    const int lane = tid & 31, wd = tid >> 5;
    {
        float awl = attn_w[lane], awh = attn_w[32 + lane];
        for (int p = wd * 16; p < wd * 16 + 16; p++) {
            int s = p >> 5, tt2 = p & 31;
            float v = hist[s][tt2][lane] * awl + hist[s][tt2][32 + lane] * awh;
#pragma unroll
            for (int o = 16; o > 0; o >>= 1) v += __shfl_xor_sync(0xffffffffu, v, o);
            if (lane == 0) sbuf[s][tt2] = v;   // pre-tanh, pre-bias
        }
    }
    __syncthreads();
    if (wd < 4) {   // warp s handles softmax over T=32 (one lane per t)
        float ab = attn_b[0];
        float sc = tanhf(sbuf[wd][lane] + ab);
        float m = sc;
#pragma unroll
        for (int o = 16; o > 0; o >>= 1) m = fmaxf(m, __shfl_xor_sync(0xffffffffu, m, o));
        float e = __expf(sc - m);
        float ssum = e;
#pragma unroll
        for (int o = 16; o > 0; o >>= 1) ssum += __shfl_xor_sync(0xffffffffu, ssum, o);
        sbuf[wd][lane] = e / ssum;
    }
    __syncthreads();
    // weighted sum -> e_old
    float eo = 0.f;
#pragma unroll
    for (int tt2 = 0; tt2 < Tt; tt2++) eo = fmaf(hist[us][tt2][uj], sbuf[us][tt2], eo);
    g_eold[(seq0 + us) * Hh + uj] = eo;
}

// ---------------------------------------------------------------------------
// Kernel 3: GNN aggregation + prediction head (fused).
// Block = (b, 64 i-rows).  Thread (r = tid/4, kq = tid%4) owns 16 k-lanes.
// e_new[i,k] = sum_j (e_i . e_j) * coef[i,j] * e_j[k]  (div deg in epilogue)
// ---------------------------------------------------------------------------
__global__ __launch_bounds__(256) void gnn_kernel(
    const float* __restrict__ pred_w,
    const float* __restrict__ pred_b,
    float* __restrict__ out)
{
    __shared__ float ejs[64 * 64];       // e_old j-tile, [jj][k]
    __shared__ float coefs[64 * 65];     // coef tile transposed, [jj][r] padded

    const int tid = threadIdx.x;
    const int r  = tid >> 2;   // 0..63 local i-row
    const int kq = tid & 3;    // k-quarter
    const int b  = blockIdx.y;
    const int i0 = blockIdx.x * 64;

    const float* eob = g_eold + (size_t)b * Nn * Hh;

    float eoi[16], acc[16];
    {
        const float4* p4 = (const float4*)(eob + (size_t)(i0 + r) * Hh + kq * 16);
#pragma unroll
        for (int q = 0; q < 4; q++) {
            float4 v = p4[q];
            eoi[4*q+0] = v.x; eoi[4*q+1] = v.y; eoi[4*q+2] = v.z; eoi[4*q+3] = v.w;
        }
    }
#pragma unroll
    for (int m = 0; m < 16; m++) acc[m] = 0.f;

    for (int j0 = 0; j0 < Nn; j0 += 64) {
        __syncthreads();
        for (int idx = tid; idx < 64 * 64; idx += 256)
            ejs[idx] = eob[(size_t)j0 * Hh + idx];
        for (int idx = tid; idx < 64 * 64; idx += 256) {
            int rr = idx >> 6, jj = idx & 63;
            coefs[jj * 65 + rr] = g_coef[(size_t)(i0 + rr) * Nn + j0 + jj];
        }
        __syncthreads();
#pragma unroll 2
        for (int jj = 0; jj < 64; jj++) {
            const float4* e4 = (const float4*)(&ejs[jj * 64 + kq * 16]);
            float4 v0 = e4[0], v1 = e4[1], v2 = e4[2], v3 = e4[3];
            float d = eoi[0] * v0.x;
            d = fmaf(eoi[1],  v0.y, d); d = fmaf(eoi[2],  v0.z, d); d = fmaf(eoi[3],  v0.w, d);
            d = fmaf(eoi[4],  v1.x, d); d = fmaf(eoi[5],  v1.y, d); d = fmaf(eoi[6],  v1.z, d);
            d = fmaf(eoi[7],  v1.w, d); d = fmaf(eoi[8],  v2.x, d); d = fmaf(eoi[9],  v2.y, d);
            d = fmaf(eoi[10], v2.z, d); d = fmaf(eoi[11], v2.w, d); d = fmaf(eoi[12], v3.x, d);
            d = fmaf(eoi[13], v3.y, d); d = fmaf(eoi[14], v3.z, d); d = fmaf(eoi[15], v3.w, d);
            d += __shfl_xor_sync(0xffffffffu, d, 1);
            d += __shfl_xor_sync(0xffffffffu, d, 2);
            float sc = d * coefs[jj * 65 + r];
            acc[0]  = fmaf(sc, v0.x, acc[0]);  acc[1]  = fmaf(sc, v0.y, acc[1]);
            acc[2]  = fmaf(sc, v0.z, acc[2]);  acc[3]  = fmaf(sc, v0.w, acc[3]);
            acc[4]  = fmaf(sc, v1.x, acc[4]);  acc[5]  = fmaf(sc, v1.y, acc[5]);
            acc[6]  = fmaf(sc, v1.z, acc[6]);  acc[7]  = fmaf(sc, v1.w, acc[7]);
            acc[8]  = fmaf(sc, v2.x, acc[8]);  acc[9]  = fmaf(sc, v2.y, acc[9]);
            acc[10] = fmaf(sc, v2.z, acc[10]); acc[11] = fmaf(sc, v2.w, acc[11]);
            acc[12] = fmaf(sc, v3.x, acc[12]); acc[13] = fmaf(sc, v3.y, acc[13]);
            acc[14] = fmaf(sc, v3.z, acc[14]); acc[15] = fmaf(sc, v3.w, acc[15]);
        }
    }

    // fused prediction head: pred = w[0:H].e_old + w[H:2H].(acc/deg) + b
    const float invdeg = 1.0f / g_deg[i0 + r];
    float p = 0.f;
#pragma unroll
    for (int m = 0; m < 16; m++) {
        p = fmaf(eoi[m],          pred_w[kq * 16 + m],      p);
        p = fmaf(acc[m] * invdeg, pred_w[64 + kq * 16 + m], p);
    }
    p += __shfl_xor_sync(0xffffffffu, p, 1);
    p += __shfl_xor_sync(0xffffffffu, p, 2);
    if (kq == 0) out[(size_t)b * Nn + i0 + r] = p + pred_b[0];
}

// ---------------------------------------------------------------------------
extern "C" void kernel_launch(void* const* d_in, const int* in_sizes, int n_in,
                              void* d_out, int out_size)
{
    const float* x      = (const float*)d_in[0];
    const float* A      = (const float*)d_in[1];
    const float* Wih    = (const float*)d_in[2];
    const float* Whh    = (const float*)d_in[3];
    const float* bih    = (const float*)d_in[4];
    const float* bhh    = (const float*)d_in[5];
    const float* attn_w = (const float*)d_in[6];
    const float* attn_b = (const float*)d_in[7];
    const float* gnn_w  = (const float*)d_in[8];
    const float* gnn_b  = (const float*)d_in[9];
    const float* pred_w = (const float*)d_in[10];
    const float* pred_b = (const float*)d_in[11];
    float* out = (float*)d_out;

    prep_kernel<<<Nn, 256>>>(A, gnn_w, gnn_b);
    lstm_kernel<<<BN / 4, 256>>>(x, Wih, Whh, bih, bhh, attn_w, attn_b);
    gnn_kernel<<<dim3(Nn / 64, Bb), 256>>>(pred_w, pred_b, out);
}